// round 1
// baseline (speedup 1.0000x reference)
#include <cuda_runtime.h>
#include <math.h>

#define B    64
#define H    1024
#define NH   8
#define HD   128
#define SQ   24
#define NE   512
#define K3H  3072
#define H4   4096

#define LOGITS_TOT (SQ*B*NE)   // 786432
#define IDX_TOT    (SQ*B*3)    // 4608

// ---------------- persistent device scratch (no allocations allowed) ----------------
__device__ float d_Wcat[(size_t)H4 * H4];     // [4096][4096] = W_ih | W_hh packed
__device__ float d_Xcat[(size_t)B * H4];      // [64][4096]  = x(3072) | h(1024)
__device__ float d_c[(size_t)B * H];
__device__ float d_gatesp[2 * (size_t)B * H4];
__device__ float d_qkvp[2 * (size_t)B * K3H];
__device__ float d_q[(size_t)B * H];
__device__ float d_Kc[(size_t)SQ * B * H];
__device__ float d_Vc[(size_t)SQ * B * H];
__device__ float d_ctx[(size_t)B * H];
__device__ float d_aop[4 * (size_t)B * H];
__device__ float d_qin[(size_t)B * H];
__device__ float d_qp[4 * (size_t)B * H];

// ---------------- init kernels ----------------
__global__ void init_wcat(const float* __restrict__ W_ih, const float* __restrict__ W_hh) {
    size_t id = (size_t)blockIdx.x * 256 + threadIdx.x;   // 16.7M elems
    int j = (int)(id >> 12);
    int k = (int)(id & 4095);
    d_Wcat[id] = (k < K3H) ? W_ih[(size_t)j * K3H + k]
                           : W_hh[(size_t)j * H + (k - K3H)];
}

__global__ void init_state(const float* __restrict__ hidden,
                           const float* __restrict__ cell,
                           const float* __restrict__ init_in) {
    int id = blockIdx.x * 256 + threadIdx.x;              // B*H4 = 262144
    int b = id >> 12;
    int k = id & 4095;
    if (k < K3H) {
        d_Xcat[id] = init_in[(size_t)b * K3H + k];
    } else {
        d_Xcat[id] = hidden[(size_t)b * H + (k - K3H)];
        d_c[(size_t)b * H + (k - K3H)] = cell[(size_t)b * H + (k - K3H)];
    }
}

// ---------------- fp32 GEMM: C_part[ky][64][N] = A[64, kslice] * W[N, kslice]^T ----------------
// M=64 fixed. Block tile 64x64, 128 threads, 8x4 microtile, double-buffered smem.
// W row-major with row stride == K. Deterministic K-split via blockIdx.y partials.
__global__ __launch_bounds__(128)
void gemm64(const float* __restrict__ A, int lda,
            const float* __restrict__ W, int K, int N,
            float* __restrict__ C, int kper)
{
    __shared__ __align__(16) float As[2][16][68];
    __shared__ __align__(16) float Ws[2][16][68];

    const int tx = threadIdx.x;
    const int tm = tx >> 4;        // 0..7  -> rows tm*8 .. tm*8+7
    const int tn = tx & 15;        // 0..15 -> cols tn*4 .. tn*4+3
    const int nblk = blockIdx.x * 64;
    const int k0 = blockIdx.y * kper;

    float acc[8][4];
#pragma unroll
    for (int i = 0; i < 8; i++)
#pragma unroll
        for (int j = 0; j < 4; j++) acc[i][j] = 0.f;

    const int nk = kper / 16;

    // A loader: scattered global (A is small/L2-resident), conflict-free STS
    // W loader: coalesced global (W is the big operand), ~2-way STS conflicts
#define LOAD_A(KT, ST)                                                              \
    {                                                                               \
        _Pragma("unroll")                                                           \
        for (int i = 0; i < 2; i++) {                                               \
            int idx = tx + i * 128;                                                 \
            int cg = idx >> 6, row = idx & 63;                                      \
            float4 v = *reinterpret_cast<const float4*>(                            \
                &A[(size_t)row * lda + (KT) + cg * 4]);                             \
            As[ST][cg * 4 + 0][row] = v.x; As[ST][cg * 4 + 1][row] = v.y;           \
            As[ST][cg * 4 + 2][row] = v.z; As[ST][cg * 4 + 3][row] = v.w;           \
        }                                                                           \
    }
#define LOAD_W(KT, ST)                                                              \
    {                                                                               \
        _Pragma("unroll")                                                           \
        for (int i = 0; i < 2; i++) {                                               \
            int idx = tx + i * 128;                                                 \
            int row = idx >> 2, cg = idx & 3;                                       \
            float4 v = *reinterpret_cast<const float4*>(                            \
                &W[(size_t)(nblk + row) * K + (KT) + cg * 4]);                      \
            Ws[ST][cg * 4 + 0][row] = v.x; Ws[ST][cg * 4 + 1][row] = v.y;           \
            Ws[ST][cg * 4 + 2][row] = v.z; Ws[ST][cg * 4 + 3][row] = v.w;           \
        }                                                                           \
    }

    LOAD_A(k0, 0);
    LOAD_W(k0, 0);
    __syncthreads();

    for (int it = 0; it < nk; it++) {
        int st = it & 1;
        if (it + 1 < nk) {
            LOAD_A(k0 + (it + 1) * 16, st ^ 1);
            LOAD_W(k0 + (it + 1) * 16, st ^ 1);
        }
#pragma unroll
        for (int kk = 0; kk < 16; kk++) {
            float a[8], bb[4];
            *reinterpret_cast<float4*>(&a[0]) = *reinterpret_cast<const float4*>(&As[st][kk][tm * 8]);
            *reinterpret_cast<float4*>(&a[4]) = *reinterpret_cast<const float4*>(&As[st][kk][tm * 8 + 4]);
            *reinterpret_cast<float4*>(&bb[0]) = *reinterpret_cast<const float4*>(&Ws[st][kk][tn * 4]);
#pragma unroll
            for (int i = 0; i < 8; i++)
#pragma unroll
                for (int j = 0; j < 4; j++)
                    acc[i][j] = fmaf(a[i], bb[j], acc[i][j]);
        }
        __syncthreads();
    }

    float* Cp = C + (size_t)blockIdx.y * B * N;
#pragma unroll
    for (int i = 0; i < 8; i++)
#pragma unroll
        for (int j = 0; j < 4; j++)
            Cp[(size_t)(tm * 8 + i) * N + nblk + tn * 4 + j] = acc[i][j];
#undef LOAD_A
#undef LOAD_W
}

// ---------------- pointwise / small kernels ----------------
__device__ __forceinline__ float sigmoidf_(float x) { return 1.f / (1.f + expf(-x)); }

__global__ void lstm_update(const float* __restrict__ b_ih, const float* __restrict__ b_hh) {
    int id = blockIdx.x * blockDim.x + threadIdx.x;  // B*H
    int b = id >> 10, j = id & 1023;
    const float* g0 = d_gatesp;
    const float* g1 = d_gatesp + (size_t)B * H4;
    size_t base = (size_t)b * H4;
    float gi = g0[base + j]        + g1[base + j]        + b_ih[j]        + b_hh[j];
    float gf = g0[base + 1024 + j] + g1[base + 1024 + j] + b_ih[1024 + j] + b_hh[1024 + j];
    float gg = g0[base + 2048 + j] + g1[base + 2048 + j] + b_ih[2048 + j] + b_hh[2048 + j];
    float go = g0[base + 3072 + j] + g1[base + 3072 + j] + b_ih[3072 + j] + b_hh[3072 + j];
    float c = sigmoidf_(gf) * d_c[(size_t)b * H + j] + sigmoidf_(gi) * tanhf(gg);
    d_c[(size_t)b * H + j] = c;
    d_Xcat[base + K3H + j] = sigmoidf_(go) * tanhf(c);
}

__global__ void qkv_scatter(const float* __restrict__ ain_b, int t) {
    int id = blockIdx.x * blockDim.x + threadIdx.x;  // B*3072
    int b = id / K3H, j = id - b * K3H;
    float v = d_qkvp[id] + d_qkvp[(size_t)B * K3H + id] + ain_b[j];
    if (j < 1024)       d_q[(size_t)b * H + j] = v;
    else if (j < 2048)  d_Kc[((size_t)t * B + b) * H + (j - 1024)] = v;
    else                d_Vc[((size_t)t * B + b) * H + (j - 2048)] = v;
}

__global__ __launch_bounds__(256) void attention_kernel(int t) {
    int b = blockIdx.x;
    int w = threadIdx.x >> 5;   // head
    int l = threadIdx.x & 31;
    __shared__ float sc[NH][32];
    const float scale = 0.08838834764831845f;  // 1/sqrt(128)

    float4 q4 = *reinterpret_cast<const float4*>(&d_q[(size_t)b * H + w * HD + l * 4]);
    for (int s = 0; s <= t; s++) {
        float4 k4 = *reinterpret_cast<const float4*>(&d_Kc[((size_t)s * B + b) * H + w * HD + l * 4]);
        float p = q4.x * k4.x + q4.y * k4.y + q4.z * k4.z + q4.w * k4.w;
#pragma unroll
        for (int off = 16; off; off >>= 1) p += __shfl_xor_sync(0xffffffffu, p, off);
        if (l == 0) sc[w][s] = p * scale;
    }
    __syncwarp();
    float val = (l <= t) ? sc[w][l] : -3.0e38f;
    float mx = val;
#pragma unroll
    for (int off = 16; off; off >>= 1) mx = fmaxf(mx, __shfl_xor_sync(0xffffffffu, mx, off));
    float e = (l <= t) ? expf(val - mx) : 0.f;
    float se = e;
#pragma unroll
    for (int off = 16; off; off >>= 1) se += __shfl_xor_sync(0xffffffffu, se, off);
    float inv = 1.f / se;

    float cx0 = 0.f, cx1 = 0.f, cx2 = 0.f, cx3 = 0.f;
    for (int s = 0; s <= t; s++) {
        float a = __shfl_sync(0xffffffffu, e, s) * inv;
        float4 v4 = *reinterpret_cast<const float4*>(&d_Vc[((size_t)s * B + b) * H + w * HD + l * 4]);
        cx0 = fmaf(a, v4.x, cx0); cx1 = fmaf(a, v4.y, cx1);
        cx2 = fmaf(a, v4.z, cx2); cx3 = fmaf(a, v4.w, cx3);
    }
    float4 o4 = make_float4(cx0, cx1, cx2, cx3);
    *reinterpret_cast<float4*>(&d_ctx[(size_t)b * H + w * HD + l * 4]) = o4;
}

__global__ void make_qin(const float* __restrict__ aout_b) {
    int id = blockIdx.x * blockDim.x + threadIdx.x;  // B*H
    int k = id & 1023;
    float ao = d_aop[id] + d_aop[(size_t)B * H + id] + d_aop[2 * (size_t)B * H + id]
             + d_aop[3 * (size_t)B * H + id] + aout_b[k];
    d_qin[id] = 0.5f * (d_Xcat[(size_t)(id >> 10) * H4 + K3H + k] + ao);
}

__global__ __launch_bounds__(256)
void logits_kernel(const float* __restrict__ enc, const float* __restrict__ qt_b,
                   float* __restrict__ out, int t) {
    int b = blockIdx.x, ch = blockIdx.y;
    __shared__ __align__(16) float q[H];
    for (int k = threadIdx.x; k < H; k += 256)
        q[k] = d_qp[(size_t)b * H + k] + d_qp[(size_t)B * H + b * H + k]
             + d_qp[2 * (size_t)B * H + b * H + k] + d_qp[3 * (size_t)B * H + b * H + k]
             + qt_b[k];
    __syncthreads();
    int w = threadIdx.x >> 5, l = threadIdx.x & 31;
    for (int ni = 0; ni < 16; ni++) {
        int n = ch * 128 + w * 16 + ni;
        const float4* e4 = reinterpret_cast<const float4*>(&enc[((size_t)b * NE + n) * H]);
        float acc = 0.f;
#pragma unroll
        for (int r = 0; r < 8; r++) {
            float4 ev = e4[l + r * 32];
            float4 qv = *reinterpret_cast<const float4*>(&q[(l + r * 32) * 4]);
            acc += ev.x * qv.x + ev.y * qv.y + ev.z * qv.z + ev.w * qv.w;
        }
#pragma unroll
        for (int off = 16; off; off >>= 1) acc += __shfl_xor_sync(0xffffffffu, acc, off);
        if (l == 0) out[(size_t)t * B * NE + (size_t)b * NE + n] = acc;
    }
}

__global__ __launch_bounds__(128)
void top3_kernel(const float* __restrict__ enc, float* __restrict__ out, int t, int out_size) {
    int b = blockIdx.x;
    __shared__ float s[NE];
    __shared__ int si[3];
    const float* lg = out + (size_t)t * B * NE + (size_t)b * NE;
    for (int n = threadIdx.x; n < NE; n += 128) s[n] = lg[n];
    __syncthreads();
    if (threadIdx.x == 0) {
        float v0 = -3.0e38f, v1 = -3.0e38f, v2 = -3.0e38f;
        int i0 = 0, i1 = 0, i2 = 0;
        for (int n = 0; n < NE; n++) {
            float v = s[n];
            if (v > v0)      { v2 = v1; i2 = i1; v1 = v0; i1 = i0; v0 = v; i0 = n; }
            else if (v > v1) { v2 = v1; i2 = i1; v1 = v; i1 = n; }
            else if (v > v2) { v2 = v; i2 = n; }
        }
        // sort indices ascending (jax: sorted top-3 indices)
        int a0 = i0, a1 = i1, a2 = i2, tmp;
        if (a0 > a1) { tmp = a0; a0 = a1; a1 = tmp; }
        if (a1 > a2) { tmp = a1; a1 = a2; a2 = tmp; }
        if (a0 > a1) { tmp = a0; a0 = a1; a1 = tmp; }
        si[0] = a0; si[1] = a1; si[2] = a2;
        if (out_size >= LOGITS_TOT + IDX_TOT) {
            float* op = out + (size_t)LOGITS_TOT + (size_t)t * B * 3 + (size_t)b * 3;
            op[0] = (float)a0; op[1] = (float)a1; op[2] = (float)a2;
        }
    }
    __syncthreads();
    for (int r = 0; r < 3; r++) {
        const float4* src = reinterpret_cast<const float4*>(&enc[((size_t)b * NE + si[r]) * H]);
        float4* dst = reinterpret_cast<float4*>(&d_Xcat[(size_t)b * H4 + r * H]);
        for (int k = threadIdx.x; k < 256; k += 128) dst[k] = src[k];
    }
}

// ---------------- launch ----------------
extern "C" void kernel_launch(void* const* d_in, const int* in_sizes, int n_in,
                              void* d_out, int out_size) {
    const float* enc     = (const float*)d_in[0];
    const float* hidden  = (const float*)d_in[1];
    const float* cell    = (const float*)d_in[2];
    const float* init_in = (const float*)d_in[4];
    int base = (in_sizes[5] > 1000) ? 5 : 6;   // skip scalar max_steps if present
    const float* W_ih   = (const float*)d_in[base + 0];
    const float* b_ih   = (const float*)d_in[base + 1];
    const float* W_hh   = (const float*)d_in[base + 2];
    const float* b_hh   = (const float*)d_in[base + 3];
    const float* ain_w  = (const float*)d_in[base + 4];
    const float* ain_b  = (const float*)d_in[base + 5];
    const float* aout_w = (const float*)d_in[base + 6];
    const float* aout_b = (const float*)d_in[base + 7];
    const float* qt_w   = (const float*)d_in[base + 8];
    const float* qt_b   = (const float*)d_in[base + 9];
    float* out = (float*)d_out;

    float *pW, *pX, *pGates, *pQkv, *pCtx, *pAop, *pQin, *pQp;
    cudaGetSymbolAddress((void**)&pW,    d_Wcat);
    cudaGetSymbolAddress((void**)&pX,    d_Xcat);
    cudaGetSymbolAddress((void**)&pGates,d_gatesp);
    cudaGetSymbolAddress((void**)&pQkv,  d_qkvp);
    cudaGetSymbolAddress((void**)&pCtx,  d_ctx);
    cudaGetSymbolAddress((void**)&pAop,  d_aop);
    cudaGetSymbolAddress((void**)&pQin,  d_qin);
    cudaGetSymbolAddress((void**)&pQp,   d_qp);

    init_wcat<<<65536, 256>>>(W_ih, W_hh);
    init_state<<<1024, 256>>>(hidden, cell, init_in);

    for (int t = 0; t < SQ; t++) {
        // LSTM gates: [64,4096] = Xcat[64,4096] @ Wcat^T, K-split 2
        gemm64<<<dim3(64, 2), 128>>>(pX, H4, pW, H4, H4, pGates, 2048);
        lstm_update<<<256, 256>>>(b_ih, b_hh);
        // fused QKV: [64,3072] = h[64,1024] @ attn_in_w^T, K-split 2
        gemm64<<<dim3(48, 2), 128>>>(pX + K3H, H4, ain_w, H, K3H, pQkv, 512);
        qkv_scatter<<<768, 256>>>(ain_b, t);
        attention_kernel<<<64, 256>>>(t);
        // attn_out: [64,1024] = ctx @ attn_out_w^T, K-split 4
        gemm64<<<dim3(16, 4), 128>>>(pCtx, H, aout_w, H, H, pAop, 256);
        make_qin<<<256, 256>>>(aout_b);
        // query: [64,1024] = qin @ qt_w^T, K-split 4
        gemm64<<<dim3(16, 4), 128>>>(pQin, H, qt_w, H, H, pQp, 256);
        logits_kernel<<<dim3(64, 4), 256>>>(enc, qt_b, out, t);
        top3_kernel<<<64, 128>>>(enc, out, t, out_size);
    }
}

// round 2
// speedup vs baseline: 1.6972x; 1.6972x over previous
#include <cuda_runtime.h>
#include <math.h>

#define B    64
#define H    1024
#define NH   8
#define HD   128
#define SQ   24
#define NE   512
#define K3H  3072
#define H4   4096

#define LOGITS_TOT (SQ*B*NE)   // 786432
#define IDX_TOT    (SQ*B*3)    // 4608

#define KS_GATES 4
#define KS_QKV   4
#define KS_SMALL 8

// ---------------- persistent device scratch (no allocations allowed) ----------------
__device__ float d_Wcat[(size_t)H4 * H4];     // [4096][4096] = W_ih | W_hh packed
__device__ float d_Xcat[(size_t)B * H4];      // [64][4096]  = x(3072) | h(1024)
__device__ float d_c[(size_t)B * H];
__device__ float d_gatesp[KS_GATES * (size_t)B * H4];
__device__ float d_qkvp[KS_QKV * (size_t)B * K3H];
__device__ float d_Kc[(size_t)SQ * B * H];
__device__ float d_Vc[(size_t)SQ * B * H];
__device__ float d_ctx[(size_t)B * H];
__device__ float d_aop[KS_SMALL * (size_t)B * H];
__device__ float d_qin[(size_t)B * H];
__device__ float d_qp[KS_SMALL * (size_t)B * H];

// ---------------- init kernels ----------------
__global__ void init_wcat(const float* __restrict__ W_ih, const float* __restrict__ W_hh) {
    size_t id = (size_t)blockIdx.x * 256 + threadIdx.x;   // 16.7M elems
    int j = (int)(id >> 12);
    int k = (int)(id & 4095);
    d_Wcat[id] = (k < K3H) ? W_ih[(size_t)j * K3H + k]
                           : W_hh[(size_t)j * H + (k - K3H)];
}

__global__ void init_state(const float* __restrict__ hidden,
                           const float* __restrict__ cell,
                           const float* __restrict__ init_in) {
    int id = blockIdx.x * 256 + threadIdx.x;              // B*H4 = 262144
    int b = id >> 12;
    int k = id & 4095;
    if (k < K3H) {
        d_Xcat[id] = init_in[(size_t)b * K3H + k];
    } else {
        d_Xcat[id] = hidden[(size_t)b * H + (k - K3H)];
        d_c[(size_t)b * H + (k - K3H)] = cell[(size_t)b * H + (k - K3H)];
    }
}

// ---------------- fp32 GEMM: C_part[ky][64][N] = A[64, kslice] * W[N, kslice]^T ----------------
// M=64 fixed. Block tile 64x64, 256 threads, 4x4 microtile, reg-staged double buffer.
// W row-major with row stride == K. Deterministic K-split via blockIdx.y partials.
__global__ __launch_bounds__(256)
void gemm64(const float* __restrict__ A, int lda,
            const float* __restrict__ W, int K, int N,
            float* __restrict__ C, int kper)
{
    __shared__ __align__(16) float As[2][16][68];
    __shared__ __align__(16) float Ws[2][16][68];

    const int tx = threadIdx.x;
    const int tr = tx >> 4;        // 0..15 -> rows tr*4 .. +3
    const int tc = tx & 15;        // 0..15 -> cols tc*4 .. +3
    const int nblk = blockIdx.x * 64;
    const int k0 = blockIdx.y * kper;

    // loader indices
    const int aRow = tx & 63, aCg = tx >> 6;   // A: 64 rows x 4 k-groups
    const int wRow = tx >> 2, wCg = tx & 3;    // W: 64 rows x 4 k-groups

    const float* Aptr = A + (size_t)aRow * lda + k0 + aCg * 4;
    const float* Wptr = W + (size_t)(nblk + wRow) * K + k0 + wCg * 4;

    float acc[4][4];
#pragma unroll
    for (int i = 0; i < 4; i++)
#pragma unroll
        for (int j = 0; j < 4; j++) acc[i][j] = 0.f;

    const int nk = kper / 16;

    // prologue: stage 0
    {
        float4 va = *reinterpret_cast<const float4*>(Aptr);
        float4 vw = *reinterpret_cast<const float4*>(Wptr);
        As[0][aCg * 4 + 0][aRow] = va.x; As[0][aCg * 4 + 1][aRow] = va.y;
        As[0][aCg * 4 + 2][aRow] = va.z; As[0][aCg * 4 + 3][aRow] = va.w;
        Ws[0][wCg * 4 + 0][wRow] = vw.x; Ws[0][wCg * 4 + 1][wRow] = vw.y;
        Ws[0][wCg * 4 + 2][wRow] = vw.z; Ws[0][wCg * 4 + 3][wRow] = vw.w;
    }
    __syncthreads();

    for (int it = 0; it < nk; it++) {
        const int st = it & 1;
        float4 va, vw;
        if (it + 1 < nk) {
            va = *reinterpret_cast<const float4*>(Aptr + (it + 1) * 16);
            vw = *reinterpret_cast<const float4*>(Wptr + (it + 1) * 16);
        }
#pragma unroll
        for (int kk = 0; kk < 16; kk++) {
            float4 a4 = *reinterpret_cast<const float4*>(&As[st][kk][tr * 4]);
            float4 b4 = *reinterpret_cast<const float4*>(&Ws[st][kk][tc * 4]);
            float a[4] = {a4.x, a4.y, a4.z, a4.w};
            float bb[4] = {b4.x, b4.y, b4.z, b4.w};
#pragma unroll
            for (int i = 0; i < 4; i++)
#pragma unroll
                for (int j = 0; j < 4; j++)
                    acc[i][j] = fmaf(a[i], bb[j], acc[i][j]);
        }
        if (it + 1 < nk) {
            const int sn = st ^ 1;
            As[sn][aCg * 4 + 0][aRow] = va.x; As[sn][aCg * 4 + 1][aRow] = va.y;
            As[sn][aCg * 4 + 2][aRow] = va.z; As[sn][aCg * 4 + 3][aRow] = va.w;
            Ws[sn][wCg * 4 + 0][wRow] = vw.x; Ws[sn][wCg * 4 + 1][wRow] = vw.y;
            Ws[sn][wCg * 4 + 2][wRow] = vw.z; Ws[sn][wCg * 4 + 3][wRow] = vw.w;
        }
        __syncthreads();
    }

    float* Cp = C + (size_t)blockIdx.y * B * N;
#pragma unroll
    for (int i = 0; i < 4; i++) {
        float4 v = make_float4(acc[i][0], acc[i][1], acc[i][2], acc[i][3]);
        *reinterpret_cast<float4*>(&Cp[(size_t)(tr * 4 + i) * N + nblk + tc * 4]) = v;
    }
}

// ---------------- pointwise / small kernels ----------------
__device__ __forceinline__ float sigmoidf_(float x) { return 1.f / (1.f + expf(-x)); }

__global__ void lstm_update(const float* __restrict__ b_ih, const float* __restrict__ b_hh) {
    int id = blockIdx.x * blockDim.x + threadIdx.x;  // B*H
    int b = id >> 10, j = id & 1023;
    size_t base = (size_t)b * H4;
    float gi = b_ih[j]        + b_hh[j];
    float gf = b_ih[1024 + j] + b_hh[1024 + j];
    float gg = b_ih[2048 + j] + b_hh[2048 + j];
    float go = b_ih[3072 + j] + b_hh[3072 + j];
#pragma unroll
    for (int s = 0; s < KS_GATES; s++) {
        const float* g = d_gatesp + (size_t)s * B * H4 + base;
        gi += g[j]; gf += g[1024 + j]; gg += g[2048 + j]; go += g[3072 + j];
    }
    float c = sigmoidf_(gf) * d_c[(size_t)b * H + j] + sigmoidf_(gi) * tanhf(gg);
    d_c[(size_t)b * H + j] = c;
    d_Xcat[base + K3H + j] = sigmoidf_(go) * tanhf(c);
}

// fused: sum qkv partials + bias, scatter K/V to cache, keep q in smem, run attention
__global__ __launch_bounds__(256) void qkv_attention(const float* __restrict__ ain_b, int t) {
    int b = blockIdx.x;
    __shared__ __align__(16) float sq[H];
    __shared__ float sc[NH][32];

    // phase 1: finalize qkv for this batch row
    for (int j = threadIdx.x; j < K3H; j += 256) {
        float v = ain_b[j];
#pragma unroll
        for (int s = 0; s < KS_QKV; s++)
            v += d_qkvp[(size_t)s * B * K3H + (size_t)b * K3H + j];
        if (j < 1024)       sq[j] = v;
        else if (j < 2048)  d_Kc[((size_t)t * B + b) * H + (j - 1024)] = v;
        else                d_Vc[((size_t)t * B + b) * H + (j - 2048)] = v;
    }
    __syncthreads();

    // phase 2: attention
    int w = threadIdx.x >> 5;   // head
    int l = threadIdx.x & 31;
    const float scale = 0.08838834764831845f;  // 1/sqrt(128)

    float4 q4 = *reinterpret_cast<const float4*>(&sq[w * HD + l * 4]);
    for (int s = 0; s <= t; s++) {
        float4 k4 = *reinterpret_cast<const float4*>(&d_Kc[((size_t)s * B + b) * H + w * HD + l * 4]);
        float p = q4.x * k4.x + q4.y * k4.y + q4.z * k4.z + q4.w * k4.w;
#pragma unroll
        for (int off = 16; off; off >>= 1) p += __shfl_xor_sync(0xffffffffu, p, off);
        if (l == 0) sc[w][s] = p * scale;
    }
    __syncwarp();
    float val = (l <= t) ? sc[w][l] : -3.0e38f;
    float mx = val;
#pragma unroll
    for (int off = 16; off; off >>= 1) mx = fmaxf(mx, __shfl_xor_sync(0xffffffffu, mx, off));
    float e = (l <= t) ? expf(val - mx) : 0.f;
    float se = e;
#pragma unroll
    for (int off = 16; off; off >>= 1) se += __shfl_xor_sync(0xffffffffu, se, off);
    float inv = 1.f / se;

    float cx0 = 0.f, cx1 = 0.f, cx2 = 0.f, cx3 = 0.f;
    for (int s = 0; s <= t; s++) {
        float a = __shfl_sync(0xffffffffu, e, s) * inv;
        float4 v4 = *reinterpret_cast<const float4*>(&d_Vc[((size_t)s * B + b) * H + w * HD + l * 4]);
        cx0 = fmaf(a, v4.x, cx0); cx1 = fmaf(a, v4.y, cx1);
        cx2 = fmaf(a, v4.z, cx2); cx3 = fmaf(a, v4.w, cx3);
    }
    float4 o4 = make_float4(cx0, cx1, cx2, cx3);
    *reinterpret_cast<float4*>(&d_ctx[(size_t)b * H + w * HD + l * 4]) = o4;
}

__global__ void make_qin(const float* __restrict__ aout_b) {
    int id = blockIdx.x * blockDim.x + threadIdx.x;  // B*H
    int k = id & 1023;
    float ao = aout_b[k];
#pragma unroll
    for (int s = 0; s < KS_SMALL; s++) ao += d_aop[(size_t)s * B * H + id];
    d_qin[id] = 0.5f * (d_Xcat[(size_t)(id >> 10) * H4 + K3H + k] + ao);
}

__global__ __launch_bounds__(256)
void logits_kernel(const float* __restrict__ enc, const float* __restrict__ qt_b,
                   float* __restrict__ out, int t) {
    int b = blockIdx.x, ch = blockIdx.y;
    __shared__ __align__(16) float q[H];
    for (int k = threadIdx.x; k < H; k += 256) {
        float v = qt_b[k];
#pragma unroll
        for (int s = 0; s < KS_SMALL; s++) v += d_qp[(size_t)s * B * H + (size_t)b * H + k];
        q[k] = v;
    }
    __syncthreads();
    int w = threadIdx.x >> 5, l = threadIdx.x & 31;
    for (int ni = 0; ni < 16; ni++) {
        int n = ch * 128 + w * 16 + ni;
        const float4* e4 = reinterpret_cast<const float4*>(&enc[((size_t)b * NE + n) * H]);
        float acc = 0.f;
#pragma unroll
        for (int r = 0; r < 8; r++) {
            float4 ev = e4[l + r * 32];
            float4 qv = *reinterpret_cast<const float4*>(&q[(l + r * 32) * 4]);
            acc += ev.x * qv.x + ev.y * qv.y + ev.z * qv.z + ev.w * qv.w;
        }
#pragma unroll
        for (int off = 16; off; off >>= 1) acc += __shfl_xor_sync(0xffffffffu, acc, off);
        if (l == 0) out[(size_t)t * B * NE + (size_t)b * NE + n] = acc;
    }
}

__global__ __launch_bounds__(128)
void top3_kernel(const float* __restrict__ enc, float* __restrict__ out, int t, int out_size) {
    int b = blockIdx.x;
    __shared__ float s[NE];
    __shared__ int si[3];
    const float* lg = out + (size_t)t * B * NE + (size_t)b * NE;
    for (int n = threadIdx.x; n < NE; n += 128) s[n] = lg[n];
    __syncthreads();
    if (threadIdx.x == 0) {
        float v0 = -3.0e38f, v1 = -3.0e38f, v2 = -3.0e38f;
        int i0 = 0, i1 = 0, i2 = 0;
        for (int n = 0; n < NE; n++) {
            float v = s[n];
            if (v > v0)      { v2 = v1; i2 = i1; v1 = v0; i1 = i0; v0 = v; i0 = n; }
            else if (v > v1) { v2 = v1; i2 = i1; v1 = v; i1 = n; }
            else if (v > v2) { v2 = v; i2 = n; }
        }
        int a0 = i0, a1 = i1, a2 = i2, tmp;
        if (a0 > a1) { tmp = a0; a0 = a1; a1 = tmp; }
        if (a1 > a2) { tmp = a1; a1 = a2; a2 = tmp; }
        if (a0 > a1) { tmp = a0; a0 = a1; a1 = tmp; }
        si[0] = a0; si[1] = a1; si[2] = a2;
        if (out_size >= LOGITS_TOT + IDX_TOT) {
            float* op = out + (size_t)LOGITS_TOT + (size_t)t * B * 3 + (size_t)b * 3;
            op[0] = (float)a0; op[1] = (float)a1; op[2] = (float)a2;
        }
    }
    __syncthreads();
    for (int r = 0; r < 3; r++) {
        const float4* src = reinterpret_cast<const float4*>(&enc[((size_t)b * NE + si[r]) * H]);
        float4* dst = reinterpret_cast<float4*>(&d_Xcat[(size_t)b * H4 + r * H]);
        for (int k = threadIdx.x; k < 256; k += 128) dst[k] = src[k];
    }
}

// ---------------- launch ----------------
extern "C" void kernel_launch(void* const* d_in, const int* in_sizes, int n_in,
                              void* d_out, int out_size) {
    const float* enc     = (const float*)d_in[0];
    const float* hidden  = (const float*)d_in[1];
    const float* cell    = (const float*)d_in[2];
    const float* init_in = (const float*)d_in[4];
    int base = (in_sizes[5] > 1000) ? 5 : 6;   // skip scalar max_steps if present
    const float* W_ih   = (const float*)d_in[base + 0];
    const float* b_ih   = (const float*)d_in[base + 1];
    const float* W_hh   = (const float*)d_in[base + 2];
    const float* b_hh   = (const float*)d_in[base + 3];
    const float* ain_w  = (const float*)d_in[base + 4];
    const float* ain_b  = (const float*)d_in[base + 5];
    const float* aout_w = (const float*)d_in[base + 6];
    const float* aout_b = (const float*)d_in[base + 7];
    const float* qt_w   = (const float*)d_in[base + 8];
    const float* qt_b   = (const float*)d_in[base + 9];
    float* out = (float*)d_out;

    float *pW, *pX, *pGates, *pQkv, *pCtx, *pAop, *pQin, *pQp;
    cudaGetSymbolAddress((void**)&pW,    d_Wcat);
    cudaGetSymbolAddress((void**)&pX,    d_Xcat);
    cudaGetSymbolAddress((void**)&pGates,d_gatesp);
    cudaGetSymbolAddress((void**)&pQkv,  d_qkvp);
    cudaGetSymbolAddress((void**)&pCtx,  d_ctx);
    cudaGetSymbolAddress((void**)&pAop,  d_aop);
    cudaGetSymbolAddress((void**)&pQin,  d_qin);
    cudaGetSymbolAddress((void**)&pQp,   d_qp);

    init_wcat<<<65536, 256>>>(W_ih, W_hh);
    init_state<<<1024, 256>>>(hidden, cell, init_in);

    for (int t = 0; t < SQ; t++) {
        // LSTM gates: [64,4096] = Xcat[64,4096] @ Wcat^T, K-split 4 -> 256 blocks
        gemm64<<<dim3(64, KS_GATES), 256>>>(pX, H4, pW, H4, H4, pGates, H4 / KS_GATES);
        lstm_update<<<256, 256>>>(b_ih, b_hh);
        // fused QKV: [64,3072] = h[64,1024] @ attn_in_w^T, K-split 4 -> 192 blocks
        gemm64<<<dim3(48, KS_QKV), 256>>>(pX + K3H, H4, ain_w, H, K3H, pQkv, H / KS_QKV);
        qkv_attention<<<64, 256>>>(ain_b, t);
        // attn_out: [64,1024] = ctx @ attn_out_w^T, K-split 8 -> 128 blocks
        gemm64<<<dim3(16, KS_SMALL), 256>>>(pCtx, H, aout_w, H, H, pAop, H / KS_SMALL);
        make_qin<<<256, 256>>>(aout_b);
        // query: [64,1024] = qin @ qt_w^T, K-split 8 -> 128 blocks
        gemm64<<<dim3(16, KS_SMALL), 256>>>(pQin, H, qt_w, H, H, pQp, H / KS_SMALL);
        logits_kernel<<<dim3(64, 4), 256>>>(enc, qt_b, out, t);
        top3_kernel<<<64, 128>>>(enc, out, t, out_size);
    }
}